// round 6
// baseline (speedup 1.0000x reference)
#include <cuda_runtime.h>
#include <math.h>

// ---------------- problem constants ----------------
#define Bb   4
#define Qq   8192
#define Ee   256
#define Hh   8
#define Ll   4
#define Pp   4
#define HDd  32
#define VLENv 21760   // 128*128 + 64*64 + 32*32 + 16*16

// ---------------- scratch (device globals; no allocation allowed) ----------------
__device__ float g_v   [(size_t)Bb * VLENv * Ee];   // value @ V_W^T        (~89 MB)
__device__ float g_off [(size_t)Bb * Qq   * Ee];    // tanh offsets         (~34 MB)
__device__ float g_attn[(size_t)Bb * Qq   * 128];   // attention logits     (~17 MB)
__device__ float g_samp[(size_t)Bb * Qq   * Ee];    // sampled output       (~34 MB)

// ---------------------------------------------------------------------------
// Generic SGEMM:  C[M,N] = act( A[M,K] @ W[N,K]^T + bias )
// Double-buffered smem: one __syncthreads per BK-tile, compute overlaps refill.
// Tile: BM=BN=128, BK=8, 256 threads, 8x8 outputs/thread.
// Requires: M%128==0, N%128==0, K%8==0, 16B-aligned pointers. (All true here.)
// ---------------------------------------------------------------------------
template<int ACT, int WITH_BIAS>
__global__ void __launch_bounds__(256) sgemm_tn(
    const float* __restrict__ A,
    const float* __restrict__ W,
    const float* __restrict__ bias,
    float* __restrict__ C,
    int M, int N, int K)
{
    constexpr int BM = 128, BN = 128, BK = 8;
    __shared__ __align__(16) float As[2][BK][BM + 4];
    __shared__ __align__(16) float Ws[2][BK][BN + 4];

    const int tid = threadIdx.x;
    const int bm  = blockIdx.y * BM;
    const int bn  = blockIdx.x * BN;

    // global->smem load mapping: each thread loads one float4 from A and one from W
    const int lrow = tid >> 1;          // 0..127
    const int kq   = (tid & 1) * 4;     // 0 or 4

    const float* Ap = A + (size_t)(bm + lrow) * K + kq;
    const float* Wp = W + (size_t)(bn + lrow) * K + kq;

    // compute mapping: 16x16 thread grid, 8x8 micro-tile
    const int ty = tid >> 4;            // 0..15
    const int tx = tid & 15;            // 0..15

    float acc[8][8];
#pragma unroll
    for (int i = 0; i < 8; i++)
#pragma unroll
        for (int j = 0; j < 8; j++) acc[i][j] = 0.f;

    // preload tile 0
    float4 a4 = *(const float4*)Ap;
    float4 w4 = *(const float4*)Wp;
    int buf = 0;
    As[0][kq + 0][lrow] = a4.x; As[0][kq + 1][lrow] = a4.y;
    As[0][kq + 2][lrow] = a4.z; As[0][kq + 3][lrow] = a4.w;
    Ws[0][kq + 0][lrow] = w4.x; Ws[0][kq + 1][lrow] = w4.y;
    Ws[0][kq + 2][lrow] = w4.z; Ws[0][kq + 3][lrow] = w4.w;
    __syncthreads();

    for (int k0 = 0; k0 < K; k0 += BK) {
        const bool has_next = (k0 + BK < K);
        if (has_next) {
            a4 = *(const float4*)(Ap + k0 + BK);
            w4 = *(const float4*)(Wp + k0 + BK);
        }

#pragma unroll
        for (int kk = 0; kk < BK; kk++) {
            float4 a0 = *(const float4*)&As[buf][kk][ty * 8];
            float4 a1 = *(const float4*)&As[buf][kk][ty * 8 + 4];
            float4 w0 = *(const float4*)&Ws[buf][kk][tx * 8];
            float4 w1 = *(const float4*)&Ws[buf][kk][tx * 8 + 4];
            float ar[8] = {a0.x, a0.y, a0.z, a0.w, a1.x, a1.y, a1.z, a1.w};
            float wr[8] = {w0.x, w0.y, w0.z, w0.w, w1.x, w1.y, w1.z, w1.w};
#pragma unroll
            for (int i = 0; i < 8; i++)
#pragma unroll
                for (int j = 0; j < 8; j++)
                    acc[i][j] = fmaf(ar[i], wr[j], acc[i][j]);
        }

        if (has_next) {
            const int nb = buf ^ 1;
            As[nb][kq + 0][lrow] = a4.x; As[nb][kq + 1][lrow] = a4.y;
            As[nb][kq + 2][lrow] = a4.z; As[nb][kq + 3][lrow] = a4.w;
            Ws[nb][kq + 0][lrow] = w4.x; Ws[nb][kq + 1][lrow] = w4.y;
            Ws[nb][kq + 2][lrow] = w4.z; Ws[nb][kq + 3][lrow] = w4.w;
            __syncthreads();
            buf = nb;
        }
    }

    // epilogue
    float bv[8];
    if (WITH_BIAS) {
        float4 b0 = *(const float4*)&bias[bn + tx * 8];
        float4 b1 = *(const float4*)&bias[bn + tx * 8 + 4];
        bv[0]=b0.x; bv[1]=b0.y; bv[2]=b0.z; bv[3]=b0.w;
        bv[4]=b1.x; bv[5]=b1.y; bv[6]=b1.z; bv[7]=b1.w;
    }
#pragma unroll
    for (int i = 0; i < 8; i++) {
        size_t row = (size_t)(bm + ty * 8 + i);
        float* crow = C + row * N + bn + tx * 8;
        float o[8];
#pragma unroll
        for (int j = 0; j < 8; j++) {
            float val = acc[i][j];
            if (WITH_BIAS) val += bv[j];
            if (ACT == 1)  val = tanhf(val);
            o[j] = val;
        }
        *(float4*)(crow)     = make_float4(o[0], o[1], o[2], o[3]);
        *(float4*)(crow + 4) = make_float4(o[4], o[5], o[6], o[7]);
    }
}

// ---------------------------------------------------------------------------
// Sampler v2: one warp per (b, q, h).
// Lane l -> (tap r = l>>1, channel-half j = l&1).
//   * softmax weight, coordinates, integer indexing computed ONCE per tap
//     (was: redundantly by all 32 lanes)
//   * each lane loads its tap's 4 bilinear corners as 4x float4 (16 channels)
//     -> LDG.128 instead of LDG.32 (4x fewer load instructions, same bytes)
//   * 16-float per-lane contribution reduced across the 16 taps with a
//     4-step shfl butterfly (xor 2,4,8,16; j-duplicates make it exact)
//   * lanes with r==0 (lane 0: j=0 half, lane 1: j=1 half) store 4x float4
// ---------------------------------------------------------------------------
__global__ void __launch_bounds__(256) sampler_kernel(
    const float* __restrict__ v,
    const float* __restrict__ off,
    const float* __restrict__ attn,
    const float* __restrict__ refp,
    float* __restrict__ outp)
{
    const int wid  = blockIdx.x * 8 + (threadIdx.x >> 5);   // (b*Q+q)*H + h
    const int lane = threadIdx.x & 31;
    const int h    = wid & 7;
    const size_t bq = (size_t)(wid >> 3);                   // b*Q + q
    const int b    = wid >> 16;                             // / (Q*H) = / 65536

    const int r   = lane >> 1;          // tap 0..15  (= l*4 + p)
    const int j   = lane & 1;           // channel half (16 floats each)
    const int lev = r >> 2;             // level 0..3
    const int Wl  = 128 >> lev;         // 128,64,32,16
    const int start = (65536 - ((Wl * Wl) << 2)) / 3;  // 0,16384,20480,21504

    // ---- softmax over the 16 taps (value duplicated across j; butterfly over
    //      xor {2,4,8,16} reduces across all 16 taps, leaves result in all lanes)
    float logit = attn[bq * 128 + h * 16 + r];
    float m = logit;
#pragma unroll
    for (int s = 2; s < 32; s <<= 1)
        m = fmaxf(m, __shfl_xor_sync(0xffffffffu, m, s));
    float e = __expf(logit - m);
    float ssum = e;
#pragma unroll
    for (int s = 2; s < 32; s <<= 1)
        ssum += __shfl_xor_sync(0xffffffffu, ssum, s);
    const float wgt = e / ssum;

    // ---- sampling location for tap r
    const float rx = refp[bq * 8 + lev * 2 + 0];
    const float ry = refp[bq * 8 + lev * 2 + 1];
    const float ox = off[bq * 256 + h * 32 + r * 2 + 0];
    const float oy = off[bq * 256 + h * 32 + r * 2 + 1];
    const float x = fminf(fmaxf(rx + ox, -1.f), 1.f);
    const float y = fminf(fmaxf(ry + oy, -1.f), 1.f);
    const float scale = 0.5f * (float)(Wl - 1);
    const float fx = (x + 1.f) * scale;
    const float fy = (y + 1.f) * scale;
    const float x0f = floorf(fx), y0f = floorf(fy);
    const float wx = fx - x0f,    wy = fy - y0f;
    int x0 = min(max((int)x0f, 0), Wl - 1);
    int x1 = min(x0 + 1, Wl - 1);
    int y0 = min(max((int)y0f, 0), Wl - 1);
    int y1 = min(y0 + 1, Wl - 1);

    // corner weights, pre-multiplied by the attention weight
    const float w00 = wgt * (1.f - wx) * (1.f - wy);
    const float w01 = wgt * wx * (1.f - wy);
    const float w10 = wgt * (1.f - wx) * wy;
    const float w11 = wgt * wx * wy;

    // ---- vectorized corner loads + bilinear combine (16 channels per lane)
    const float* base = v + ((size_t)b * VLENv + start) * Ee + h * HDd + j * 16;
    const float4* p00 = (const float4*)(base + (size_t)(y0 * Wl + x0) * Ee);
    const float4* p01 = (const float4*)(base + (size_t)(y0 * Wl + x1) * Ee);
    const float4* p10 = (const float4*)(base + (size_t)(y1 * Wl + x0) * Ee);
    const float4* p11 = (const float4*)(base + (size_t)(y1 * Wl + x1) * Ee);

    float acc[16];
#pragma unroll
    for (int k = 0; k < 4; k++) {
        const float4 c00 = p00[k];
        const float4 c01 = p01[k];
        const float4 c10 = p10[k];
        const float4 c11 = p11[k];
        acc[4*k+0] = w00*c00.x + w01*c01.x + w10*c10.x + w11*c11.x;
        acc[4*k+1] = w00*c00.y + w01*c01.y + w10*c10.y + w11*c11.y;
        acc[4*k+2] = w00*c00.z + w01*c01.z + w10*c10.z + w11*c11.z;
        acc[4*k+3] = w00*c00.w + w01*c01.w + w10*c10.w + w11*c11.w;
    }

    // ---- reduce across the 16 taps (same-j lanes)
#pragma unroll
    for (int s = 2; s < 32; s <<= 1) {
#pragma unroll
        for (int k = 0; k < 16; k++)
            acc[k] += __shfl_xor_sync(0xffffffffu, acc[k], s);
    }

    // ---- store: lane 0 writes channels [0,16), lane 1 writes [16,32)
    if (r == 0) {
        float4* o = (float4*)(outp + bq * 256 + h * HDd + j * 16);
        o[0] = make_float4(acc[0],  acc[1],  acc[2],  acc[3]);
        o[1] = make_float4(acc[4],  acc[5],  acc[6],  acc[7]);
        o[2] = make_float4(acc[8],  acc[9],  acc[10], acc[11]);
        o[3] = make_float4(acc[12], acc[13], acc[14], acc[15]);
    }
}

// ---------------------------------------------------------------------------
// kernel_launch
// inputs (metadata order): 0 queries, 1 ref_points, 2 value, 3 spatial_shapes,
//                          4 V_W, 5 off_W, 6 off_b, 7 attn_W, 8 attn_b, 9 out_W
// output: float32 (B, Q, E)
// ---------------------------------------------------------------------------
extern "C" void kernel_launch(void* const* d_in, const int* in_sizes, int n_in,
                              void* d_out, int out_size)
{
    const float* queries = (const float*)d_in[0];
    const float* refp    = (const float*)d_in[1];
    const float* value   = (const float*)d_in[2];
    const float* V_W     = (const float*)d_in[4];
    const float* off_W   = (const float*)d_in[5];
    const float* off_b   = (const float*)d_in[6];
    const float* attn_W  = (const float*)d_in[7];
    const float* attn_b  = (const float*)d_in[8];
    const float* out_W   = (const float*)d_in[9];
    float* out = (float*)d_out;

    float *pv, *poff, *pattn, *psamp;
    cudaGetSymbolAddress((void**)&pv,    g_v);
    cudaGetSymbolAddress((void**)&poff,  g_off);
    cudaGetSymbolAddress((void**)&pattn, g_attn);
    cudaGetSymbolAddress((void**)&psamp, g_samp);

    const int MV = Bb * VLENv;   // 87040  (% 128 == 0)
    const int MQ = Bb * Qq;      // 32768  (% 128 == 0)

    dim3 blk(256);

    // 1) v = value @ V_W^T
    sgemm_tn<0, 0><<<dim3(Ee / 128, MV / 128), blk>>>(value, V_W, nullptr, pv, MV, Ee, Ee);
    // 2) off = tanh(queries @ off_W^T + off_b)
    sgemm_tn<1, 1><<<dim3(Ee / 128, MQ / 128), blk>>>(queries, off_W, off_b, poff, MQ, Ee, Ee);
    // 3) attn logits = queries @ attn_W^T + attn_b
    sgemm_tn<0, 1><<<dim3(128 / 128, MQ / 128), blk>>>(queries, attn_W, attn_b, pattn, MQ, 128, Ee);
    // 4) softmax + bilinear sampling + weighted sum
    sampler_kernel<<<(Bb * Qq * Hh) / 8, 256>>>(pv, poff, pattn, refp, psamp);
    // 5) out = samp @ out_W^T
    sgemm_tn<0, 0><<<dim3(Ee / 128, MQ / 128), blk>>>(psamp, out_W, nullptr, out, MQ, Ee, Ee);
}

// round 7
// speedup vs baseline: 1.2696x; 1.2696x over previous
#include <cuda_runtime.h>
#include <math.h>

// ---------------- problem constants ----------------
#define Bb   4
#define Qq   8192
#define Ee   256
#define Hh   8
#define Ll   4
#define Pp   4
#define HDd  32
#define VLENv 21760   // 128*128 + 64*64 + 32*32 + 16*16

// ---------------- scratch (device globals; no allocation allowed) ----------------
__device__ float g_v   [(size_t)Bb * VLENv * Ee];   // value @ V_W^T        (~89 MB)
__device__ float g_off [(size_t)Bb * Qq   * Ee];    // tanh offsets         (~34 MB)
__device__ float g_attn[(size_t)Bb * Qq   * 128];   // attention logits     (~17 MB)
__device__ float g_samp[(size_t)Bb * Qq   * Ee];    // sampled output       (~34 MB)

// ---------------------------------------------------------------------------
// Generic SGEMM:  C[M,N] = act( A[M,K] @ W[N,K]^T + bias )
// Double-buffered smem: one __syncthreads per BK-tile, compute overlaps refill.
// Tile: BM=BN=128, BK=8, 256 threads, 8x8 outputs/thread.
// (Measured at ~40 TF/s = FFMA pipe ceiling; unchanged this round.)
// ---------------------------------------------------------------------------
template<int ACT, int WITH_BIAS>
__global__ void __launch_bounds__(256) sgemm_tn(
    const float* __restrict__ A,
    const float* __restrict__ W,
    const float* __restrict__ bias,
    float* __restrict__ C,
    int M, int N, int K)
{
    constexpr int BM = 128, BN = 128, BK = 8;
    __shared__ __align__(16) float As[2][BK][BM + 4];
    __shared__ __align__(16) float Ws[2][BK][BN + 4];

    const int tid = threadIdx.x;
    const int bm  = blockIdx.y * BM;
    const int bn  = blockIdx.x * BN;

    const int lrow = tid >> 1;          // 0..127
    const int kq   = (tid & 1) * 4;     // 0 or 4

    const float* Ap = A + (size_t)(bm + lrow) * K + kq;
    const float* Wp = W + (size_t)(bn + lrow) * K + kq;

    const int ty = tid >> 4;            // 0..15
    const int tx = tid & 15;            // 0..15

    float acc[8][8];
#pragma unroll
    for (int i = 0; i < 8; i++)
#pragma unroll
        for (int j = 0; j < 8; j++) acc[i][j] = 0.f;

    float4 a4 = *(const float4*)Ap;
    float4 w4 = *(const float4*)Wp;
    int buf = 0;
    As[0][kq + 0][lrow] = a4.x; As[0][kq + 1][lrow] = a4.y;
    As[0][kq + 2][lrow] = a4.z; As[0][kq + 3][lrow] = a4.w;
    Ws[0][kq + 0][lrow] = w4.x; Ws[0][kq + 1][lrow] = w4.y;
    Ws[0][kq + 2][lrow] = w4.z; Ws[0][kq + 3][lrow] = w4.w;
    __syncthreads();

    for (int k0 = 0; k0 < K; k0 += BK) {
        const bool has_next = (k0 + BK < K);
        if (has_next) {
            a4 = *(const float4*)(Ap + k0 + BK);
            w4 = *(const float4*)(Wp + k0 + BK);
        }

#pragma unroll
        for (int kk = 0; kk < BK; kk++) {
            float4 a0 = *(const float4*)&As[buf][kk][ty * 8];
            float4 a1 = *(const float4*)&As[buf][kk][ty * 8 + 4];
            float4 w0 = *(const float4*)&Ws[buf][kk][tx * 8];
            float4 w1 = *(const float4*)&Ws[buf][kk][tx * 8 + 4];
            float ar[8] = {a0.x, a0.y, a0.z, a0.w, a1.x, a1.y, a1.z, a1.w};
            float wr[8] = {w0.x, w0.y, w0.z, w0.w, w1.x, w1.y, w1.z, w1.w};
#pragma unroll
            for (int i = 0; i < 8; i++)
#pragma unroll
                for (int j = 0; j < 8; j++)
                    acc[i][j] = fmaf(ar[i], wr[j], acc[i][j]);
        }

        if (has_next) {
            const int nb = buf ^ 1;
            As[nb][kq + 0][lrow] = a4.x; As[nb][kq + 1][lrow] = a4.y;
            As[nb][kq + 2][lrow] = a4.z; As[nb][kq + 3][lrow] = a4.w;
            Ws[nb][kq + 0][lrow] = w4.x; Ws[nb][kq + 1][lrow] = w4.y;
            Ws[nb][kq + 2][lrow] = w4.z; Ws[nb][kq + 3][lrow] = w4.w;
            __syncthreads();
            buf = nb;
        }
    }

    float bv[8];
    if (WITH_BIAS) {
        float4 b0 = *(const float4*)&bias[bn + tx * 8];
        float4 b1 = *(const float4*)&bias[bn + tx * 8 + 4];
        bv[0]=b0.x; bv[1]=b0.y; bv[2]=b0.z; bv[3]=b0.w;
        bv[4]=b1.x; bv[5]=b1.y; bv[6]=b1.z; bv[7]=b1.w;
    }
#pragma unroll
    for (int i = 0; i < 8; i++) {
        size_t row = (size_t)(bm + ty * 8 + i);
        float* crow = C + row * N + bn + tx * 8;
        float o[8];
#pragma unroll
        for (int j = 0; j < 8; j++) {
            float val = acc[i][j];
            if (WITH_BIAS) val += bv[j];
            if (ACT == 1)  val = tanhf(val);
            o[j] = val;
        }
        *(float4*)(crow)     = make_float4(o[0], o[1], o[2], o[3]);
        *(float4*)(crow + 4) = make_float4(o[4], o[5], o[6], o[7]);
    }
}

// ---------------------------------------------------------------------------
// Sampler v3: one warp per (b, q, h). Corner-cooperative loads.
//
// Phase 1 (lane-parallel over taps, r = lane & 15):
//   softmax weight + sampling coords + 4 corner position indices + 4
//   pre-multiplied corner weights, written to smem (lanes 0..15).
// Phase 2 (loop over 16 taps): lane = (corner c = lane>>3, chan-quad k = lane&7).
//   ONE LDG.128 per tap covers all 4 corners x all 32 channels:
//   8 lanes per 128B line, fully coalesced -> 4 L1 wavefronts/tap
//   (v2 spent 16 wavefronts/tap: lane-pairs revisited each line 4x).
//   Per-lane FMA accumulation; corner reduction via shfl xor {8,16};
//   lanes 0..7 store one coalesced 128B output row.
// ---------------------------------------------------------------------------
__global__ void __launch_bounds__(256) sampler_kernel(
    const float* __restrict__ v,
    const float* __restrict__ off,
    const float* __restrict__ attn,
    const float* __restrict__ refp,
    float* __restrict__ outp)
{
    __shared__ int   s_pos[8][16][4];   // [warp][tap][corner] position index
    __shared__ float s_w  [8][16][4];   // [warp][tap][corner] premult weight

    const int wslot = threadIdx.x >> 5;
    const int wid   = blockIdx.x * 8 + wslot;     // (b*Q+q)*H + h
    const int lane  = threadIdx.x & 31;
    const int h     = wid & 7;
    const size_t bq = (size_t)(wid >> 3);         // b*Q + q
    const int b     = wid >> 16;                  // / (Q*H) = / 65536

    // ================= phase 1: per-tap params (all lanes mirror r=lane&15)
    const int r   = lane & 15;
    const int lev = r >> 2;
    const int Wl  = 128 >> lev;                   // 128,64,32,16
    const int start = (65536 - ((Wl * Wl) << 2)) / 3;  // 0,16384,20480,21504

    // softmax over 16 taps: xor strides 1..8 reduce each 16-lane half
    // independently; halves hold identical data so results agree.
    float logit = attn[bq * 128 + h * 16 + r];
    float m = logit;
#pragma unroll
    for (int s = 1; s < 16; s <<= 1)
        m = fmaxf(m, __shfl_xor_sync(0xffffffffu, m, s));
    float e = __expf(logit - m);
    float ssum = e;
#pragma unroll
    for (int s = 1; s < 16; s <<= 1)
        ssum += __shfl_xor_sync(0xffffffffu, ssum, s);
    const float wgt = e / ssum;

    const float rx = refp[bq * 8 + lev * 2 + 0];
    const float ry = refp[bq * 8 + lev * 2 + 1];
    const float ox = off[bq * 256 + h * 32 + r * 2 + 0];
    const float oy = off[bq * 256 + h * 32 + r * 2 + 1];
    const float x = fminf(fmaxf(rx + ox, -1.f), 1.f);
    const float y = fminf(fmaxf(ry + oy, -1.f), 1.f);
    const float scale = 0.5f * (float)(Wl - 1);
    const float fx = (x + 1.f) * scale;
    const float fy = (y + 1.f) * scale;
    const float x0f = floorf(fx), y0f = floorf(fy);
    const float wx = fx - x0f,    wy = fy - y0f;
    const int x0 = min(max((int)x0f, 0), Wl - 1);
    const int x1 = min(x0 + 1, Wl - 1);
    const int y0 = min(max((int)y0f, 0), Wl - 1);
    const int y1 = min(y0 + 1, Wl - 1);

    if (lane < 16) {
        s_pos[wslot][r][0] = start + y0 * Wl + x0;
        s_pos[wslot][r][1] = start + y0 * Wl + x1;
        s_pos[wslot][r][2] = start + y1 * Wl + x0;
        s_pos[wslot][r][3] = start + y1 * Wl + x1;
        s_w  [wslot][r][0] = wgt * (1.f - wx) * (1.f - wy);
        s_w  [wslot][r][1] = wgt * wx * (1.f - wy);
        s_w  [wslot][r][2] = wgt * (1.f - wx) * wy;
        s_w  [wslot][r][3] = wgt * wx * wy;
    }
    __syncwarp();

    // ================= phase 2: cooperative gather
    const int c = lane >> 3;                       // corner 0..3
    const int k = lane & 7;                        // channel quad 0..7
    const float* vbase = v + (size_t)b * VLENv * Ee + h * HDd + k * 4;

    float ax = 0.f, ay = 0.f, az = 0.f, aw = 0.f;
#pragma unroll
    for (int t = 0; t < 16; t++) {
        const int   pos = s_pos[wslot][t][c];      // broadcast LDS (8 lanes/addr)
        const float wc  = s_w  [wslot][t][c];
        const float4 d = *(const float4*)(vbase + (size_t)pos * Ee);
        ax = fmaf(wc, d.x, ax);
        ay = fmaf(wc, d.y, ay);
        az = fmaf(wc, d.z, az);
        aw = fmaf(wc, d.w, aw);
    }

    // reduce the 4 corner groups (xor 8: c0<->c1,c2<->c3; xor 16: pairs)
#pragma unroll
    for (int s = 8; s < 32; s <<= 1) {
        ax += __shfl_xor_sync(0xffffffffu, ax, s);
        ay += __shfl_xor_sync(0xffffffffu, ay, s);
        az += __shfl_xor_sync(0xffffffffu, az, s);
        aw += __shfl_xor_sync(0xffffffffu, aw, s);
    }

    if (lane < 8) {
        *(float4*)(outp + bq * 256 + h * HDd + k * 4) = make_float4(ax, ay, az, aw);
    }
}

// ---------------------------------------------------------------------------
// kernel_launch
// inputs (metadata order): 0 queries, 1 ref_points, 2 value, 3 spatial_shapes,
//                          4 V_W, 5 off_W, 6 off_b, 7 attn_W, 8 attn_b, 9 out_W
// output: float32 (B, Q, E)
// ---------------------------------------------------------------------------
extern "C" void kernel_launch(void* const* d_in, const int* in_sizes, int n_in,
                              void* d_out, int out_size)
{
    const float* queries = (const float*)d_in[0];
    const float* refp    = (const float*)d_in[1];
    const float* value   = (const float*)d_in[2];
    const float* V_W     = (const float*)d_in[4];
    const float* off_W   = (const float*)d_in[5];
    const float* off_b   = (const float*)d_in[6];
    const float* attn_W  = (const float*)d_in[7];
    const float* attn_b  = (const float*)d_in[8];
    const float* out_W   = (const float*)d_in[9];
    float* out = (float*)d_out;

    float *pv, *poff, *pattn, *psamp;
    cudaGetSymbolAddress((void**)&pv,    g_v);
    cudaGetSymbolAddress((void**)&poff,  g_off);
    cudaGetSymbolAddress((void**)&pattn, g_attn);
    cudaGetSymbolAddress((void**)&psamp, g_samp);

    const int MV = Bb * VLENv;   // 87040  (% 128 == 0)
    const int MQ = Bb * Qq;      // 32768  (% 128 == 0)

    dim3 blk(256);

    // 1) v = value @ V_W^T
    sgemm_tn<0, 0><<<dim3(Ee / 128, MV / 128), blk>>>(value, V_W, nullptr, pv, MV, Ee, Ee);
    // 2) off = tanh(queries @ off_W^T + off_b)
    sgemm_tn<1, 1><<<dim3(Ee / 128, MQ / 128), blk>>>(queries, off_W, off_b, poff, MQ, Ee, Ee);
    // 3) attn logits = queries @ attn_W^T + attn_b
    sgemm_tn<0, 1><<<dim3(128 / 128, MQ / 128), blk>>>(queries, attn_W, attn_b, pattn, MQ, 128, Ee);
    // 4) softmax + bilinear sampling + weighted sum
    sampler_kernel<<<(Bb * Qq * Hh) / 8, 256>>>(pv, poff, pattn, refp, psamp);
    // 5) out = samp @ out_W^T
    sgemm_tn<0, 0><<<dim3(Ee / 128, MQ / 128), blk>>>(psamp, out_W, nullptr, out, MQ, Ee, Ee);
}

// round 9
// speedup vs baseline: 2.2240x; 1.7518x over previous
#include <cuda_runtime.h>
#include <cuda_bf16.h>
#include <math.h>
#include <stdint.h>

// ---------------- problem constants ----------------
#define Bb   4
#define Qq   8192
#define Ee   256
#define Hh   8
#define HDd  32
#define VLENv 21760            // 128*128 + 64*64 + 32*32 + 16*16
#define MV   (Bb * VLENv)      // 87040  rows (value)
#define MQ   (Bb * Qq)         // 32768  rows (queries / samp)
#define KE   768               // extended K = 3 * 256 (split-bf16)

// ---------------- scratch (device globals; no allocation allowed) ----------------
__device__ float g_v   [(size_t)MV * Ee];     // value @ V_W^T      (~89 MB)
__device__ float g_off [(size_t)MQ * Ee];     // tanh offsets       (~34 MB)
__device__ float g_attn[(size_t)MQ * 128];    // attention logits   (~17 MB)
__device__ float g_samp[(size_t)MQ * Ee];     // sampled output     (~34 MB)

__device__ __nv_bfloat16 g_val_ext [(size_t)MV * KE];   // ~134 MB
__device__ __nv_bfloat16 g_q_ext   [(size_t)MQ * KE];   // ~50 MB
__device__ __nv_bfloat16 g_samp_ext[(size_t)MQ * KE];   // ~50 MB
__device__ __nv_bfloat16 g_w_ext   [4][(size_t)256 * KE]; // V_W, off_W, attn_W, out_W

// ============================================================================
// Split-bf16 conversion: float[rows,256] -> bf16[rows,768]
// MODE 0 (activations): [hi | lo | hi]   MODE 1 (weights): [hi | hi | lo]
// Pairing over extended K: ah*wh + al*wh + ah*wl  (drops al*wl ~ 2^-16)
// ============================================================================
template<int MODE>
__global__ void convert_ext(const float* __restrict__ in,
                            __nv_bfloat16* __restrict__ out, int rows)
{
    int idx = blockIdx.x * blockDim.x + threadIdx.x;  // one float2 per thread
    if (idx >= rows * 128) return;
    int row = idx >> 7, j = idx & 127;
    float2 x = ((const float2*)in)[idx];
    __nv_bfloat16 hx = __float2bfloat16(x.x);
    __nv_bfloat16 hy = __float2bfloat16(x.y);
    float lx = x.x - __bfloat162float(hx);
    float ly = x.y - __bfloat162float(hy);
    __nv_bfloat162 hi; hi.x = hx; hi.y = hy;
    __nv_bfloat162 lo; lo.x = __float2bfloat16(lx); lo.y = __float2bfloat16(ly);
    __nv_bfloat162* o = (__nv_bfloat162*)(out + (size_t)row * KE) + j;
    o[0]   = hi;
    o[128] = MODE ? hi : lo;
    o[256] = MODE ? lo : hi;
}

// ============================================================================
// HMMA GEMM (arch-neutral PTX: ldmatrix + mma.sync + cp.async, sm_80+ path)
//   C[M,N] = act( A_ext[M,768] @ W_ext[N,768]^T + bias )
// Both operands K-major -> TN pattern: non-trans ldmatrix, mma .row.col.
// CTA tile 128x128xK64, 8 warps (4m x 2n), warp tile 32x64.
// SMEM: 2 stages x (A 16KB + B 16KB) = 64KB, SW128 xor swizzle.
// ============================================================================
#define STAGE_BYTES 32768
#define SMEM_TOTAL_MM (2 * STAGE_BYTES)

__device__ __forceinline__ uint32_t smem_u32(const void* p) {
    uint32_t a;
    asm("{ .reg .u64 t; cvta.to.shared.u64 t, %1; cvt.u32.u64 %0, t; }" : "=r"(a) : "l"(p));
    return a;
}

__device__ __forceinline__ void cp16(uint32_t s, const void* g) {
    asm volatile("cp.async.cg.shared.global [%0], [%1], 16;" :: "r"(s), "l"(g));
}
__device__ __forceinline__ void cp_commit() {
    asm volatile("cp.async.commit_group;" ::: "memory");
}

__device__ __forceinline__ void ldsm_x4(uint32_t* r, uint32_t addr) {
    asm volatile("ldmatrix.sync.aligned.m8n8.x4.shared.b16 {%0,%1,%2,%3}, [%4];"
                 : "=r"(r[0]), "=r"(r[1]), "=r"(r[2]), "=r"(r[3]) : "r"(addr));
}
__device__ __forceinline__ void mma16816(float* d, const uint32_t* a, const uint32_t* b) {
    asm volatile("mma.sync.aligned.m16n8k16.row.col.f32.bf16.bf16.f32 "
                 "{%0,%1,%2,%3}, {%4,%5,%6,%7}, {%8,%9}, {%0,%1,%2,%3};"
                 : "+f"(d[0]), "+f"(d[1]), "+f"(d[2]), "+f"(d[3])
                 : "r"(a[0]), "r"(a[1]), "r"(a[2]), "r"(a[3]), "r"(b[0]), "r"(b[1]));
}

template<int ACT, int WITH_BIAS>
__global__ void __launch_bounds__(256, 2) mm_hmma(
    const __nv_bfloat16* __restrict__ A,    // [M, 768] row-major
    const __nv_bfloat16* __restrict__ Wx,   // [N, 768] row-major
    const float* __restrict__ bias,
    float* __restrict__ C, int M, int N)
{
    extern __shared__ char smem[];
    const uint32_t sb = smem_u32(smem);

    const int tid  = threadIdx.x;
    const int wid  = tid >> 5;
    const int lane = tid & 31;
    const int wm   = wid & 3;            // 4 m-warps (32 rows each)
    const int wn   = wid >> 2;           // 2 n-warps (64 cols each)
    const int bm   = blockIdx.y * 128;
    const int bn   = blockIdx.x * 128;

    const char* Ab = (const char*)A  + (size_t)bm * (KE * 2);   // row = 1536 B
    const char* Wb = (const char*)Wx + (size_t)bn * (KE * 2);

    // ---- global->smem loader (one 64-col K-chunk = 128 rows x 128 B per matrix)
    const int lrow = tid >> 1;                 // for u = i*256+tid: row = u>>3
    (void)lrow;

    auto load_stage = [&](int c, int st) {
        const uint32_t sbuf = sb + st * STAGE_BYTES;
#pragma unroll
        for (int i = 0; i < 4; i++) {
            int u = i * 256 + tid;
            int row = u >> 3, ku = u & 7;
            uint32_t bo = row * 128 + ku * 16;
            uint32_t sw = bo ^ ((bo >> 3) & 0x70);
            cp16(sbuf + sw, Ab + (size_t)row * 1536 + c * 128 + ku * 16);
        }
#pragma unroll
        for (int i = 0; i < 4; i++) {
            int u = i * 256 + tid;
            int row = u >> 3, ku = u & 7;
            uint32_t bo = row * 128 + ku * 16;
            uint32_t sw = bo ^ ((bo >> 3) & 0x70);
            cp16(sbuf + 16384 + sw, Wb + (size_t)row * 1536 + c * 128 + ku * 16);
        }
        cp_commit();
    };

    float acc[2][8][4];
#pragma unroll
    for (int i = 0; i < 2; i++)
#pragma unroll
        for (int j = 0; j < 8; j++)
#pragma unroll
            for (int e = 0; e < 4; e++) acc[i][j][e] = 0.f;

    // ---- per-lane ldmatrix address components (swizzle mask constant per lane)
    const uint32_t xorm = (uint32_t)(lane & 7) << 4;
    // A: rows wm*32 + mm*16 + (lane&15); chunk16 = ks*2 + (lane>>4)
    const int arow = wm * 32 + (lane & 15);
    const int ahi  = lane >> 4;
    // B: rows wn*64 + jp*16 + ((lane>>4)&1)*8 + (lane&7); chunk16 = ks*2 + ((lane>>3)&1)
    const int brow = wn * 64 + ((lane >> 4) & 1) * 8 + (lane & 7);
    const int bhi  = (lane >> 3) & 1;

    load_stage(0, 0);
    load_stage(1, 1);

    for (int c = 0; c < 12; ++c) {
        if (c < 11) { asm volatile("cp.async.wait_group 1;" ::: "memory"); }
        else        { asm volatile("cp.async.wait_group 0;" ::: "memory"); }
        __syncthreads();

        const uint32_t sbuf = sb + (c & 1) * STAGE_BYTES;
        const uint32_t sbufB = sbuf + 16384;

#pragma unroll
        for (int ks = 0; ks < 4; ks++) {
            uint32_t a[2][4];
#pragma unroll
            for (int mm = 0; mm < 2; mm++) {
                uint32_t bo = (uint32_t)(arow + mm * 16) * 128
                            + ((uint32_t)((ks * 2 + ahi) * 16) ^ xorm);
                ldsm_x4(a[mm], sbuf + bo);
            }
            uint32_t b[4][4];
#pragma unroll
            for (int jp = 0; jp < 4; jp++) {
                uint32_t bo = (uint32_t)(brow + jp * 16) * 128
                            + ((uint32_t)((ks * 2 + bhi) * 16) ^ xorm);
                ldsm_x4(b[jp], sbufB + bo);
            }
#pragma unroll
            for (int mm = 0; mm < 2; mm++)
#pragma unroll
                for (int jn = 0; jn < 8; jn++)
                    mma16816(acc[mm][jn], a[mm], &b[jn >> 1][(jn & 1) * 2]);
        }
        __syncthreads();
        if (c + 2 < 12) load_stage(c + 2, c & 1);
    }

    // ---- epilogue: fragment (l>>2, (l&3)*2) mapping; fused bias/tanh
    const int r0 = bm + wm * 32 + (lane >> 2);
    const int c0 = bn + wn * 64 + (lane & 3) * 2;
#pragma unroll
    for (int mm = 0; mm < 2; mm++) {
#pragma unroll
        for (int jn = 0; jn < 8; jn++) {
            const int row = r0 + mm * 16;
            const int col = c0 + jn * 8;
            float v0 = acc[mm][jn][0], v1 = acc[mm][jn][1];
            float v2 = acc[mm][jn][2], v3 = acc[mm][jn][3];
            if (WITH_BIAS) {
                float b0 = bias[col], b1 = bias[col + 1];
                v0 += b0; v1 += b1; v2 += b0; v3 += b1;
            }
            if (ACT == 1) {
                v0 = tanhf(v0); v1 = tanhf(v1); v2 = tanhf(v2); v3 = tanhf(v3);
            }
            *(float2*)(C + (size_t)row * N + col)       = make_float2(v0, v1);
            *(float2*)(C + (size_t)(row + 8) * N + col) = make_float2(v2, v3);
        }
    }
}

// ---------------------------------------------------------------------------
// Sampler v3 (unchanged; 126 us, L1-wavefront optimized)
// ---------------------------------------------------------------------------
__global__ void __launch_bounds__(256) sampler_kernel(
    const float* __restrict__ v,
    const float* __restrict__ off,
    const float* __restrict__ attn,
    const float* __restrict__ refp,
    float* __restrict__ outp)
{
    __shared__ int   s_pos[8][16][4];
    __shared__ float s_w  [8][16][4];

    const int wslot = threadIdx.x >> 5;
    const int wid   = blockIdx.x * 8 + wslot;
    const int lane  = threadIdx.x & 31;
    const int h     = wid & 7;
    const size_t bq = (size_t)(wid >> 3);
    const int b     = wid >> 16;

    const int r   = lane & 15;
    const int lev = r >> 2;
    const int Wl  = 128 >> lev;
    const int start = (65536 - ((Wl * Wl) << 2)) / 3;

    float logit = attn[bq * 128 + h * 16 + r];
    float m = logit;
#pragma unroll
    for (int s = 1; s < 16; s <<= 1)
        m = fmaxf(m, __shfl_xor_sync(0xffffffffu, m, s));
    float e = __expf(logit - m);
    float ssum = e;
#pragma unroll
    for (int s = 1; s < 16; s <<= 1)
        ssum += __shfl_xor_sync(0xffffffffu, ssum, s);
    const float wgt = e / ssum;

    const float rx = refp[bq * 8 + lev * 2 + 0];
    const float ry = refp[bq * 8 + lev * 2 + 1];
    const float ox = off[bq * 256 + h * 32 + r * 2 + 0];
    const float oy = off[bq * 256 + h * 32 + r * 2 + 1];
    const float x = fminf(fmaxf(rx + ox, -1.f), 1.f);
    const float y = fminf(fmaxf(ry + oy, -1.f), 1.f);
    const float scale = 0.5f * (float)(Wl - 1);
    const float fx = (x + 1.f) * scale;
    const float fy = (y + 1.f) * scale;
    const float x0f = floorf(fx), y0f = floorf(fy);
    const float wx = fx - x0f,    wy = fy - y0f;
    const int x0 = min(max((int)x0f, 0), Wl - 1);
    const int x1 = min(x0 + 1, Wl - 1);
    const int y0 = min(max((int)y0f, 0), Wl - 1);
    const int y1 = min(y0 + 1, Wl - 1);

    if (lane < 16) {
        s_pos[wslot][r][0] = start + y0 * Wl + x0;
        s_pos[wslot][r][1] = start + y0 * Wl + x1;
        s_pos[wslot][r][2] = start + y1 * Wl + x0;
        s_pos[wslot][r][3] = start + y1 * Wl + x1;
        s_w  [wslot][r][0] = wgt * (1.f - wx) * (1.f - wy);
        s_w  [wslot][r][1] = wgt * wx * (1.f - wy);
        s_w  [wslot][r][2] = wgt * (1.f - wx) * wy;
        s_w  [wslot][r][3] = wgt * wx * wy;
    }
    __syncwarp();

    const int c = lane >> 3;
    const int k = lane & 7;
    const float* vbase = v + (size_t)b * VLENv * Ee + h * HDd + k * 4;

    float ax = 0.f, ay = 0.f, az = 0.f, aw = 0.f;
#pragma unroll
    for (int t = 0; t < 16; t++) {
        const int   pos = s_pos[wslot][t][c];
        const float wc  = s_w  [wslot][t][c];
        const float4 d = *(const float4*)(vbase + (size_t)pos * Ee);
        ax = fmaf(wc, d.x, ax);
        ay = fmaf(wc, d.y, ay);
        az = fmaf(wc, d.z, az);
        aw = fmaf(wc, d.w, aw);
    }
#pragma unroll
    for (int s = 8; s < 32; s <<= 1) {
        ax += __shfl_xor_sync(0xffffffffu, ax, s);
        ay += __shfl_xor_sync(0xffffffffu, ay, s);
        az += __shfl_xor_sync(0xffffffffu, az, s);
        aw += __shfl_xor_sync(0xffffffffu, aw, s);
    }
    if (lane < 8) {
        *(float4*)(outp + bq * 256 + h * HDd + k * 4) = make_float4(ax, ay, az, aw);
    }
}

// ---------------------------------------------------------------------------
// kernel_launch
// inputs: 0 queries, 1 ref_points, 2 value, 3 spatial_shapes,
//         4 V_W, 5 off_W, 6 off_b, 7 attn_W, 8 attn_b, 9 out_W
// ---------------------------------------------------------------------------
extern "C" void kernel_launch(void* const* d_in, const int* in_sizes, int n_in,
                              void* d_out, int out_size)
{
    const float* queries = (const float*)d_in[0];
    const float* refp    = (const float*)d_in[1];
    const float* value   = (const float*)d_in[2];
    const float* V_W     = (const float*)d_in[4];
    const float* off_W   = (const float*)d_in[5];
    const float* off_b   = (const float*)d_in[6];
    const float* attn_W  = (const float*)d_in[7];
    const float* attn_b  = (const float*)d_in[8];
    const float* out_W   = (const float*)d_in[9];
    float* out = (float*)d_out;

    float *pv, *poff, *pattn, *psamp;
    __nv_bfloat16 *pval_e, *pq_e, *psamp_e, *pw_e;
    cudaGetSymbolAddress((void**)&pv,      g_v);
    cudaGetSymbolAddress((void**)&poff,    g_off);
    cudaGetSymbolAddress((void**)&pattn,   g_attn);
    cudaGetSymbolAddress((void**)&psamp,   g_samp);
    cudaGetSymbolAddress((void**)&pval_e,  g_val_ext);
    cudaGetSymbolAddress((void**)&pq_e,    g_q_ext);
    cudaGetSymbolAddress((void**)&psamp_e, g_samp_ext);
    cudaGetSymbolAddress((void**)&pw_e,    g_w_ext);
    __nv_bfloat16* w_v    = pw_e + 0 * (size_t)256 * KE;
    __nv_bfloat16* w_off  = pw_e + 1 * (size_t)256 * KE;
    __nv_bfloat16* w_attn = pw_e + 2 * (size_t)256 * KE;
    __nv_bfloat16* w_out  = pw_e + 3 * (size_t)256 * KE;

    cudaFuncSetAttribute(mm_hmma<0, 0>, cudaFuncAttributeMaxDynamicSharedMemorySize, SMEM_TOTAL_MM);
    cudaFuncSetAttribute(mm_hmma<1, 1>, cudaFuncAttributeMaxDynamicSharedMemorySize, SMEM_TOTAL_MM);
    cudaFuncSetAttribute(mm_hmma<0, 1>, cudaFuncAttributeMaxDynamicSharedMemorySize, SMEM_TOTAL_MM);

    // ---- split-bf16 conversions
    convert_ext<1><<<(256 * 128 + 255) / 256, 256>>>(V_W,    w_v,    256);
    convert_ext<1><<<(256 * 128 + 255) / 256, 256>>>(off_W,  w_off,  256);
    convert_ext<1><<<(128 * 128 + 255) / 256, 256>>>(attn_W, w_attn, 128);
    convert_ext<1><<<(256 * 128 + 255) / 256, 256>>>(out_W,  w_out,  256);
    convert_ext<0><<<(MV * 128 + 255) / 256, 256>>>(value,   pval_e, MV);
    convert_ext<0><<<(MQ * 128 + 255) / 256, 256>>>(queries, pq_e,   MQ);

    // ---- tensor-core GEMMs (split-bf16 via mma.sync, fp32 accumulate)
    // 1) v = value @ V_W^T
    mm_hmma<0, 0><<<dim3(2, MV / 128), 256, SMEM_TOTAL_MM>>>(pval_e, w_v, nullptr, pv, MV, 256);
    // 2) off = tanh(queries @ off_W^T + off_b)
    mm_hmma<1, 1><<<dim3(2, MQ / 128), 256, SMEM_TOTAL_MM>>>(pq_e, w_off, off_b, poff, MQ, 256);
    // 3) attn logits = queries @ attn_W^T + attn_b
    mm_hmma<0, 1><<<dim3(1, MQ / 128), 256, SMEM_TOTAL_MM>>>(pq_e, w_attn, attn_b, pattn, MQ, 128);

    // ---- softmax + bilinear sampling + weighted sum
    sampler_kernel<<<(Bb * Qq * Hh) / 8, 256>>>(pv, poff, pattn, refp, psamp);

    // ---- final projection
    convert_ext<0><<<(MQ * 128 + 255) / 256, 256>>>(psamp, psamp_e, MQ);
    mm_hmma<0, 0><<<dim3(2, MQ / 128), 256, SMEM_TOTAL_MM>>>(psamp_e, w_out, nullptr, out, MQ, 256);
}

// round 10
// speedup vs baseline: 2.3831x; 1.0716x over previous
#include <cuda_runtime.h>
#include <cuda_bf16.h>
#include <math.h>
#include <stdint.h>

// ---------------- problem constants ----------------
#define Bb   4
#define Qq   8192
#define Ee   256
#define Hh   8
#define HDd  32
#define VLENv 21760            // 128*128 + 64*64 + 32*32 + 16*16
#define MV   (Bb * VLENv)      // 87040  rows (value)
#define MQ   (Bb * Qq)         // 32768  rows (queries / samp)
#define KE   768               // extended K = 3 * 256 (split-bf16)

// ---------------- scratch (device globals; no allocation allowed) ----------------
__device__ float g_v   [(size_t)MV * Ee];     // value @ V_W^T      (~89 MB)
__device__ float g_off [(size_t)MQ * Ee];     // tanh offsets       (~34 MB)
__device__ float g_attn[(size_t)MQ * 128];    // attention logits   (~17 MB)

__device__ __nv_bfloat16 g_val_ext [(size_t)MV * KE];   // ~134 MB
__device__ __nv_bfloat16 g_q_ext   [(size_t)MQ * KE];   // ~50 MB
__device__ __nv_bfloat16 g_samp_ext[(size_t)MQ * KE];   // ~50 MB (written by sampler)
__device__ __nv_bfloat16 g_w_ext   [4][(size_t)256 * KE]; // V_W, off_W, attn_W, out_W

// ============================================================================
// Split-bf16 conversion: float[rows,256] -> bf16[rows,768]
// MODE 0 (activations): [hi | lo | hi]   MODE 1 (weights): [hi | hi | lo]
// Pairing over extended K: ah*wh + al*wh + ah*wl  (drops al*wl ~ 2^-16)
// ============================================================================
__device__ __forceinline__ void split_store(const float2& x,
                                            __nv_bfloat16* o, int mode)
{
    __nv_bfloat16 hx = __float2bfloat16(x.x);
    __nv_bfloat16 hy = __float2bfloat16(x.y);
    float lx = x.x - __bfloat162float(hx);
    float ly = x.y - __bfloat162float(hy);
    __nv_bfloat162 hi; hi.x = hx; hi.y = hy;
    __nv_bfloat162 lo; lo.x = __float2bfloat16(lx); lo.y = __float2bfloat16(ly);
    __nv_bfloat162* p = (__nv_bfloat162*)o;
    p[0]   = hi;
    p[128] = mode ? hi : lo;
    p[256] = mode ? lo : hi;
}

template<int MODE>
__global__ void convert_ext(const float* __restrict__ in,
                            __nv_bfloat16* __restrict__ out, int rows)
{
    int idx = blockIdx.x * blockDim.x + threadIdx.x;  // one float2 per thread
    if (idx >= rows * 128) return;
    int row = idx >> 7, j = idx & 127;
    float2 x = ((const float2*)in)[idx];
    split_store(x, out + (size_t)row * KE + j * 2, MODE);
}

// All 4 weight matrices in ONE launch (they are tiny; 4 separate launches
// were pure launch-overhead). Segments (float2 counts): 32768/32768/16384/32768.
__global__ void convert_w4(const float* __restrict__ w0, const float* __restrict__ w1,
                           const float* __restrict__ w2, const float* __restrict__ w3,
                           __nv_bfloat16* __restrict__ o0, __nv_bfloat16* __restrict__ o1,
                           __nv_bfloat16* __restrict__ o2, __nv_bfloat16* __restrict__ o3)
{
    int idx = blockIdx.x * 256 + threadIdx.x;
    const float* in; __nv_bfloat16* out; int local;
    if      (idx <  32768) { in = w0; out = o0; local = idx; }
    else if (idx <  65536) { in = w1; out = o1; local = idx -  32768; }
    else if (idx <  81920) { in = w2; out = o2; local = idx -  65536; }
    else if (idx < 114688) { in = w3; out = o3; local = idx -  81920; }
    else return;
    int row = local >> 7, j = local & 127;
    float2 x = ((const float2*)in)[local];
    split_store(x, out + (size_t)row * KE + j * 2, 1);
}

// ============================================================================
// HMMA GEMM (arch-neutral PTX: ldmatrix + mma.sync + cp.async, sm_80+ path)
//   C[M,N] = act( A_ext[M,768] @ W_ext[N,768]^T + bias )
// CTA tile 128x128xK64, 8 warps (4m x 2n), warp tile 32x64.
// SMEM: 2 stages x (A 16KB + B 16KB) = 64KB, SW128 xor swizzle.
// ============================================================================
#define STAGE_BYTES 32768
#define SMEM_TOTAL_MM (2 * STAGE_BYTES)

__device__ __forceinline__ uint32_t smem_u32(const void* p) {
    uint32_t a;
    asm("{ .reg .u64 t; cvta.to.shared.u64 t, %1; cvt.u32.u64 %0, t; }" : "=r"(a) : "l"(p));
    return a;
}
__device__ __forceinline__ void cp16(uint32_t s, const void* g) {
    asm volatile("cp.async.cg.shared.global [%0], [%1], 16;" :: "r"(s), "l"(g));
}
__device__ __forceinline__ void cp_commit() {
    asm volatile("cp.async.commit_group;" ::: "memory");
}
__device__ __forceinline__ void ldsm_x4(uint32_t* r, uint32_t addr) {
    asm volatile("ldmatrix.sync.aligned.m8n8.x4.shared.b16 {%0,%1,%2,%3}, [%4];"
                 : "=r"(r[0]), "=r"(r[1]), "=r"(r[2]), "=r"(r[3]) : "r"(addr));
}
__device__ __forceinline__ void mma16816(float* d, const uint32_t* a, const uint32_t* b) {
    asm volatile("mma.sync.aligned.m16n8k16.row.col.f32.bf16.bf16.f32 "
                 "{%0,%1,%2,%3}, {%4,%5,%6,%7}, {%8,%9}, {%0,%1,%2,%3};"
                 : "+f"(d[0]), "+f"(d[1]), "+f"(d[2]), "+f"(d[3])
                 : "r"(a[0]), "r"(a[1]), "r"(a[2]), "r"(a[3]), "r"(b[0]), "r"(b[1]));
}

template<int ACT, int WITH_BIAS>
__global__ void __launch_bounds__(256, 2) mm_hmma(
    const __nv_bfloat16* __restrict__ A,    // [M, 768] row-major
    const __nv_bfloat16* __restrict__ Wx,   // [N, 768] row-major
    const float* __restrict__ bias,
    float* __restrict__ C, int M, int N)
{
    extern __shared__ char smem[];
    const uint32_t sb = smem_u32(smem);

    const int tid  = threadIdx.x;
    const int wid  = tid >> 5;
    const int lane = tid & 31;
    const int wm   = wid & 3;            // 4 m-warps (32 rows each)
    const int wn   = wid >> 2;           // 2 n-warps (64 cols each)
    const int bm   = blockIdx.y * 128;
    const int bn   = blockIdx.x * 128;

    const char* Ab = (const char*)A  + (size_t)bm * (KE * 2);   // row = 1536 B
    const char* Wb = (const char*)Wx + (size_t)bn * (KE * 2);

    auto load_stage = [&](int c, int st) {
        const uint32_t sbuf = sb + st * STAGE_BYTES;
#pragma unroll
        for (int i = 0; i < 4; i++) {
            int u = i * 256 + tid;
            int row = u >> 3, ku = u & 7;
            uint32_t bo = row * 128 + ku * 16;
            uint32_t sw = bo ^ ((bo >> 3) & 0x70);
            cp16(sbuf + sw, Ab + (size_t)row * 1536 + c * 128 + ku * 16);
        }
#pragma unroll
        for (int i = 0; i < 4; i++) {
            int u = i * 256 + tid;
            int row = u >> 3, ku = u & 7;
            uint32_t bo = row * 128 + ku * 16;
            uint32_t sw = bo ^ ((bo >> 3) & 0x70);
            cp16(sbuf + 16384 + sw, Wb + (size_t)row * 1536 + c * 128 + ku * 16);
        }
        cp_commit();
    };

    float acc[2][8][4];
#pragma unroll
    for (int i = 0; i < 2; i++)
#pragma unroll
        for (int j = 0; j < 8; j++)
#pragma unroll
            for (int e = 0; e < 4; e++) acc[i][j][e] = 0.f;

    const uint32_t xorm = (uint32_t)(lane & 7) << 4;
    const int arow = wm * 32 + (lane & 15);
    const int ahi  = lane >> 4;
    const int brow = wn * 64 + ((lane >> 4) & 1) * 8 + (lane & 7);
    const int bhi  = (lane >> 3) & 1;

    load_stage(0, 0);
    load_stage(1, 1);

    for (int c = 0; c < 12; ++c) {
        if (c < 11) { asm volatile("cp.async.wait_group 1;" ::: "memory"); }
        else        { asm volatile("cp.async.wait_group 0;" ::: "memory"); }
        __syncthreads();

        const uint32_t sbuf  = sb + (c & 1) * STAGE_BYTES;
        const uint32_t sbufB = sbuf + 16384;

#pragma unroll
        for (int ks = 0; ks < 4; ks++) {
            uint32_t a[2][4];
#pragma unroll
            for (int mm = 0; mm < 2; mm++) {
                uint32_t bo = (uint32_t)(arow + mm * 16) * 128
                            + ((uint32_t)((ks * 2 + ahi) * 16) ^ xorm);
                ldsm_x4(a[mm], sbuf + bo);
            }
            uint32_t b[4][4];
#pragma unroll
            for (int jp = 0; jp < 4; jp++) {
                uint32_t bo = (uint32_t)(brow + jp * 16) * 128
                            + ((uint32_t)((ks * 2 + bhi) * 16) ^ xorm);
                ldsm_x4(b[jp], sbufB + bo);
            }
#pragma unroll
            for (int mm = 0; mm < 2; mm++)
#pragma unroll
                for (int jn = 0; jn < 8; jn++)
                    mma16816(acc[mm][jn], a[mm], &b[jn >> 1][(jn & 1) * 2]);
        }
        __syncthreads();
        if (c + 2 < 12) load_stage(c + 2, c & 1);
    }

    const int r0 = bm + wm * 32 + (lane >> 2);
    const int c0 = bn + wn * 64 + (lane & 3) * 2;
#pragma unroll
    for (int mm = 0; mm < 2; mm++) {
#pragma unroll
        for (int jn = 0; jn < 8; jn++) {
            const int row = r0 + mm * 16;
            const int col = c0 + jn * 8;
            float v0 = acc[mm][jn][0], v1 = acc[mm][jn][1];
            float v2 = acc[mm][jn][2], v3 = acc[mm][jn][3];
            if (WITH_BIAS) {
                float b0 = bias[col], b1 = bias[col + 1];
                v0 += b0; v1 += b1; v2 += b0; v3 += b1;
            }
            if (ACT == 1) {
                v0 = tanhf(v0); v1 = tanhf(v1); v2 = tanhf(v2); v3 = tanhf(v3);
            }
            *(float2*)(C + (size_t)row * N + col)       = make_float2(v0, v1);
            *(float2*)(C + (size_t)(row + 8) * N + col) = make_float2(v2, v3);
        }
    }
}

// ---------------------------------------------------------------------------
// Sampler v4: identical gather math to v3, but the epilogue writes the
// split-bf16 extended layout [hi | lo | hi] directly into g_samp_ext
// (same rounding the convert kernel performed -> identical numerics),
// killing a 34MB fp32 write + 34MB read + one kernel launch.
// ---------------------------------------------------------------------------
__global__ void __launch_bounds__(256) sampler_kernel(
    const float* __restrict__ v,
    const float* __restrict__ off,
    const float* __restrict__ attn,
    const float* __restrict__ refp,
    __nv_bfloat16* __restrict__ outp)   // [MQ, 768] ext layout
{
    __shared__ int   s_pos[8][16][4];
    __shared__ float s_w  [8][16][4];

    const int wslot = threadIdx.x >> 5;
    const int wid   = blockIdx.x * 8 + wslot;
    const int lane  = threadIdx.x & 31;
    const int h     = wid & 7;
    const size_t bq = (size_t)(wid >> 3);
    const int b     = wid >> 16;

    const int r   = lane & 15;
    const int lev = r >> 2;
    const int Wl  = 128 >> lev;
    const int start = (65536 - ((Wl * Wl) << 2)) / 3;

    float logit = attn[bq * 128 + h * 16 + r];
    float m = logit;
#pragma unroll
    for (int s = 1; s < 16; s <<= 1)
        m = fmaxf(m, __shfl_xor_sync(0xffffffffu, m, s));
    float e = __expf(logit - m);
    float ssum = e;
#pragma unroll
    for (int s = 1; s < 16; s <<= 1)
        ssum += __shfl_xor_sync(0xffffffffu, ssum, s);
    const float wgt = e / ssum;

    const float rx = refp[bq * 8 + lev * 2 + 0];
    const float ry = refp[bq * 8 + lev * 2 + 1];
    const float ox = off[bq * 256 + h * 32 + r * 2 + 0];
    const float oy = off[bq * 256 + h * 32 + r * 2 + 1];
    const float x = fminf(fmaxf(rx + ox, -1.f), 1.f);
    const float y = fminf(fmaxf(ry + oy, -1.f), 1.f);
    const float scale = 0.5f * (float)(Wl - 1);
    const float fx = (x + 1.f) * scale;
    const float fy = (y + 1.f) * scale;
    const float x0f = floorf(fx), y0f = floorf(fy);
    const float wx = fx - x0f,    wy = fy - y0f;
    const int x0 = min(max((int)x0f, 0), Wl - 1);
    const int x1 = min(x0 + 1, Wl - 1);
    const int y0 = min(max((int)y0f, 0), Wl - 1);
    const int y1 = min(y0 + 1, Wl - 1);

    if (lane < 16) {
        s_pos[wslot][r][0] = start + y0 * Wl + x0;
        s_pos[wslot][r][1] = start + y0 * Wl + x1;
        s_pos[wslot][r][2] = start + y1 * Wl + x0;
        s_pos[wslot][r][3] = start + y1 * Wl + x1;
        s_w  [wslot][r][0] = wgt * (1.f - wx) * (1.f - wy);
        s_w  [wslot][r][1] = wgt * wx * (1.f - wy);
        s_w  [wslot][r][2] = wgt * (1.f - wx) * wy;
        s_w  [wslot][r][3] = wgt * wx * wy;
    }
    __syncwarp();

    const int c = lane >> 3;
    const int k = lane & 7;
    const float* vbase = v + (size_t)b * VLENv * Ee + h * HDd + k * 4;

    float ax = 0.f, ay = 0.f, az = 0.f, aw = 0.f;
#pragma unroll
    for (int t = 0; t < 16; t++) {
        const int   pos = s_pos[wslot][t][c];
        const float wc  = s_w  [wslot][t][c];
        const float4 d = *(const float4*)(vbase + (size_t)pos * Ee);
        ax = fmaf(wc, d.x, ax);
        ay = fmaf(wc, d.y, ay);
        az = fmaf(wc, d.z, az);
        aw = fmaf(wc, d.w, aw);
    }
#pragma unroll
    for (int s = 8; s < 32; s <<= 1) {
        ax += __shfl_xor_sync(0xffffffffu, ax, s);
        ay += __shfl_xor_sync(0xffffffffu, ay, s);
        az += __shfl_xor_sync(0xffffffffu, az, s);
        aw += __shfl_xor_sync(0xffffffffu, aw, s);
    }

    if (lane < 8) {
        // split-bf16 ext store: hi @ col, lo @ col+256, hi @ col+512
        __nv_bfloat16 h0 = __float2bfloat16(ax);
        __nv_bfloat16 h1 = __float2bfloat16(ay);
        __nv_bfloat16 h2 = __float2bfloat16(az);
        __nv_bfloat16 h3 = __float2bfloat16(aw);
        union { __nv_bfloat162 v2[2]; uint2 u; } hi, lo;
        hi.v2[0].x = h0; hi.v2[0].y = h1; hi.v2[1].x = h2; hi.v2[1].y = h3;
        lo.v2[0].x = __float2bfloat16(ax - __bfloat162float(h0));
        lo.v2[0].y = __float2bfloat16(ay - __bfloat162float(h1));
        lo.v2[1].x = __float2bfloat16(az - __bfloat162float(h2));
        lo.v2[1].y = __float2bfloat16(aw - __bfloat162float(h3));
        __nv_bfloat16* o = outp + bq * KE + h * HDd + k * 4;
        *(uint2*)(o)       = hi.u;
        *(uint2*)(o + 256) = lo.u;
        *(uint2*)(o + 512) = hi.u;
    }
}

// ---------------------------------------------------------------------------
// kernel_launch — forked-graph schedule:
//   branch A (stream 0): conv_val -> GEMM1(value)
//   branch B (s1):       conv_w4, conv_q -> GEMM2(off) -> GEMM3(attn)
//   join -> sampler (writes samp_ext) -> GEMM4(out)
// inputs: 0 queries, 1 ref_points, 2 value, 3 spatial_shapes,
//         4 V_W, 5 off_W, 6 off_b, 7 attn_W, 8 attn_b, 9 out_W
// ---------------------------------------------------------------------------
extern "C" void kernel_launch(void* const* d_in, const int* in_sizes, int n_in,
                              void* d_out, int out_size)
{
    const float* queries = (const float*)d_in[0];
    const float* refp    = (const float*)d_in[1];
    const float* value   = (const float*)d_in[2];
    const float* V_W     = (const float*)d_in[4];
    const float* off_W   = (const float*)d_in[5];
    const float* off_b   = (const float*)d_in[6];
    const float* attn_W  = (const float*)d_in[7];
    const float* attn_b  = (const float*)d_in[8];
    const float* out_W   = (const float*)d_in[9];
    float* out = (float*)d_out;

    float *pv, *poff, *pattn;
    __nv_bfloat16 *pval_e, *pq_e, *psamp_e, *pw_e;
    cudaGetSymbolAddress((void**)&pv,      g_v);
    cudaGetSymbolAddress((void**)&poff,    g_off);
    cudaGetSymbolAddress((void**)&pattn,   g_attn);
    cudaGetSymbolAddress((void**)&pval_e,  g_val_ext);
    cudaGetSymbolAddress((void**)&pq_e,    g_q_ext);
    cudaGetSymbolAddress((void**)&psamp_e, g_samp_ext);
    cudaGetSymbolAddress((void**)&pw_e,    g_w_ext);
    __nv_bfloat16* w_v    = pw_e + 0 * (size_t)256 * KE;
    __nv_bfloat16* w_off  = pw_e + 1 * (size_t)256 * KE;
    __nv_bfloat16* w_attn = pw_e + 2 * (size_t)256 * KE;
    __nv_bfloat16* w_out  = pw_e + 3 * (size_t)256 * KE;

    cudaFuncSetAttribute(mm_hmma<0, 0>, cudaFuncAttributeMaxDynamicSharedMemorySize, SMEM_TOTAL_MM);
    cudaFuncSetAttribute(mm_hmma<1, 1>, cudaFuncAttributeMaxDynamicSharedMemorySize, SMEM_TOTAL_MM);
    cudaFuncSetAttribute(mm_hmma<0, 1>, cudaFuncAttributeMaxDynamicSharedMemorySize, SMEM_TOTAL_MM);

    // side stream + fork/join events (host objects; created per call — the
    // harness calls kernel_launch only a handful of times, replays the graph)
    cudaStream_t s1;
    cudaStreamCreateWithFlags(&s1, cudaStreamNonBlocking);
    cudaEvent_t eFork, eJoin;
    cudaEventCreateWithFlags(&eFork, cudaEventDisableTiming);
    cudaEventCreateWithFlags(&eJoin, cudaEventDisableTiming);

    cudaEventRecord(eFork, 0);
    cudaStreamWaitEvent(s1, eFork, 0);

    // ---- branch A (stream 0): value path
    convert_ext<0><<<(MV * 128 + 255) / 256, 256>>>(value, pval_e, MV);
    mm_hmma<0, 0><<<dim3(2, MV / 128), 256, SMEM_TOTAL_MM>>>(pval_e, w_v, nullptr, pv, MV, 256);

    // ---- branch B (s1): weights + query path
    convert_w4<<<448, 256, 0, s1>>>(V_W, off_W, attn_W, out_W, w_v, w_off, w_attn, w_out);
    convert_ext<0><<<(MQ * 128 + 255) / 256, 256, 0, s1>>>(queries, pq_e, MQ);
    mm_hmma<1, 1><<<dim3(2, MQ / 128), 256, SMEM_TOTAL_MM, s1>>>(pq_e, w_off, off_b, poff, MQ, 256);
    mm_hmma<0, 1><<<dim3(1, MQ / 128), 256, SMEM_TOTAL_MM, s1>>>(pq_e, w_attn, attn_b, pattn, MQ, 128);

    cudaEventRecord(eJoin, s1);
    cudaStreamWaitEvent(0, eJoin, 0);

    // ---- join: sampler (writes split-bf16 ext directly) -> final projection
    sampler_kernel<<<(Bb * Qq * Hh) / 8, 256>>>(pv, poff, pattn, refp, psamp_e);
    mm_hmma<0, 0><<<dim3(2, MQ / 128), 256, SMEM_TOTAL_MM>>>(psamp_e, w_out, nullptr, out, MQ, 256);
}

// round 11
// speedup vs baseline: 2.3934x; 1.0043x over previous
#include <cuda_runtime.h>
#include <cuda_bf16.h>
#include <math.h>
#include <stdint.h>

// ---------------- problem constants ----------------
#define Bb   4
#define Qq   8192
#define Ee   256
#define Hh   8
#define HDd  32
#define VLENv 21760            // 128*128 + 64*64 + 32*32 + 16*16
#define MV   (Bb * VLENv)      // 87040  rows (value)
#define MQ   (Bb * Qq)         // 32768  rows (queries / samp)
#define KE   768               // extended K = 3 * 256 (split-bf16)

// ---------------- scratch (device globals; no allocation allowed) ----------------
__device__ float g_v   [(size_t)MV * Ee];     // value @ V_W^T      (~89 MB)
__device__ float g_off [(size_t)MQ * Ee];     // tanh offsets       (~34 MB)
__device__ float g_attn[(size_t)MQ * 128];    // attention logits   (~17 MB)

__device__ __nv_bfloat16 g_val_ext [(size_t)MV * KE];   // ~134 MB
__device__ __nv_bfloat16 g_q_ext   [(size_t)MQ * KE];   // ~50 MB
__device__ __nv_bfloat16 g_samp_ext[(size_t)MQ * KE];   // ~50 MB (written by sampler)
__device__ __nv_bfloat16 g_w_ext   [4][(size_t)256 * KE]; // V_W, off_W, attn_W, out_W

// ============================================================================
// Split-bf16 conversion: float[rows,256] -> bf16[rows,768]
// MODE 0 (activations): [hi | lo | hi]   MODE 1 (weights): [hi | hi | lo]
// Pairing over extended K: ah*wh + al*wh + ah*wl  (drops al*wl ~ 2^-16)
// ============================================================================
__device__ __forceinline__ void split_store(const float2& x,
                                            __nv_bfloat16* o, int mode)
{
    __nv_bfloat16 hx = __float2bfloat16(x.x);
    __nv_bfloat16 hy = __float2bfloat16(x.y);
    float lx = x.x - __bfloat162float(hx);
    float ly = x.y - __bfloat162float(hy);
    __nv_bfloat162 hi; hi.x = hx; hi.y = hy;
    __nv_bfloat162 lo; lo.x = __float2bfloat16(lx); lo.y = __float2bfloat16(ly);
    __nv_bfloat162* p = (__nv_bfloat162*)o;
    p[0]   = hi;
    p[128] = mode ? hi : lo;
    p[256] = mode ? lo : hi;
}

template<int MODE>
__global__ void convert_ext(const float* __restrict__ in,
                            __nv_bfloat16* __restrict__ out, int rows)
{
    int idx = blockIdx.x * blockDim.x + threadIdx.x;  // one float2 per thread
    if (idx >= rows * 128) return;
    int row = idx >> 7, j = idx & 127;
    float2 x = ((const float2*)in)[idx];
    split_store(x, out + (size_t)row * KE + j * 2, MODE);
}

// All 4 weight matrices in ONE launch (they are tiny; 4 separate launches
// were pure launch-overhead). Segments (float2 counts): 32768/32768/16384/32768.
__global__ void convert_w4(const float* __restrict__ w0, const float* __restrict__ w1,
                           const float* __restrict__ w2, const float* __restrict__ w3,
                           __nv_bfloat16* __restrict__ o0, __nv_bfloat16* __restrict__ o1,
                           __nv_bfloat16* __restrict__ o2, __nv_bfloat16* __restrict__ o3)
{
    int idx = blockIdx.x * 256 + threadIdx.x;
    const float* in; __nv_bfloat16* out; int local;
    if      (idx <  32768) { in = w0; out = o0; local = idx; }
    else if (idx <  65536) { in = w1; out = o1; local = idx -  32768; }
    else if (idx <  81920) { in = w2; out = o2; local = idx -  65536; }
    else if (idx < 114688) { in = w3; out = o3; local = idx -  81920; }
    else return;
    int row = local >> 7, j = local & 127;
    float2 x = ((const float2*)in)[local];
    split_store(x, out + (size_t)row * KE + j * 2, 1);
}

// ============================================================================
// HMMA GEMM (arch-neutral PTX: ldmatrix + mma.sync + cp.async, sm_80+ path)
//   C[M,N] = act( A_ext[M,768] @ W_ext[N,768]^T + bias )
// CTA tile 128x128xK64, 8 warps (4m x 2n), warp tile 32x64.
// SMEM: 2 stages x (A 16KB + B 16KB) = 64KB, SW128 xor swizzle.
// ============================================================================
#define STAGE_BYTES 32768
#define SMEM_TOTAL_MM (2 * STAGE_BYTES)

__device__ __forceinline__ uint32_t smem_u32(const void* p) {
    uint32_t a;
    asm("{ .reg .u64 t; cvta.to.shared.u64 t, %1; cvt.u32.u64 %0, t; }" : "=r"(a) : "l"(p));
    return a;
}
__device__ __forceinline__ void cp16(uint32_t s, const void* g) {
    asm volatile("cp.async.cg.shared.global [%0], [%1], 16;" :: "r"(s), "l"(g));
}
__device__ __forceinline__ void cp_commit() {
    asm volatile("cp.async.commit_group;" ::: "memory");
}
__device__ __forceinline__ void ldsm_x4(uint32_t* r, uint32_t addr) {
    asm volatile("ldmatrix.sync.aligned.m8n8.x4.shared.b16 {%0,%1,%2,%3}, [%4];"
                 : "=r"(r[0]), "=r"(r[1]), "=r"(r[2]), "=r"(r[3]) : "r"(addr));
}
__device__ __forceinline__ void mma16816(float* d, const uint32_t* a, const uint32_t* b) {
    asm volatile("mma.sync.aligned.m16n8k16.row.col.f32.bf16.bf16.f32 "
                 "{%0,%1,%2,%3}, {%4,%5,%6,%7}, {%8,%9}, {%0,%1,%2,%3};"
                 : "+f"(d[0]), "+f"(d[1]), "+f"(d[2]), "+f"(d[3])
                 : "r"(a[0]), "r"(a[1]), "r"(a[2]), "r"(a[3]), "r"(b[0]), "r"(b[1]));
}

template<int ACT, int WITH_BIAS>
__global__ void __launch_bounds__(256, 2) mm_hmma(
    const __nv_bfloat16* __restrict__ A,    // [M, 768] row-major
    const __nv_bfloat16* __restrict__ Wx,   // [N, 768] row-major
    const float* __restrict__ bias,
    float* __restrict__ C, int M, int N)
{
    extern __shared__ char smem[];
    const uint32_t sb = smem_u32(smem);

    const int tid  = threadIdx.x;
    const int wid  = tid >> 5;
    const int lane = tid & 31;
    const int wm   = wid & 3;            // 4 m-warps (32 rows each)
    const int wn   = wid >> 2;           // 2 n-warps (64 cols each)
    const int bm   = blockIdx.y * 128;
    const int bn   = blockIdx.x * 128;

    const char* Ab = (const char*)A  + (size_t)bm * (KE * 2);   // row = 1536 B
    const char* Wb = (const char*)Wx + (size_t)bn * (KE * 2);

    auto load_stage = [&](int c, int st) {
        const uint32_t sbuf = sb + st * STAGE_BYTES;
#pragma unroll
        for (int i = 0; i < 4; i++) {
            int u = i * 256 + tid;
            int row = u >> 3, ku = u & 7;
            uint32_t bo = row * 128 + ku * 16;
            uint32_t sw = bo ^ ((bo >> 3) & 0x70);
            cp16(sbuf + sw, Ab + (size_t)row * 1536 + c * 128 + ku * 16);
        }
#pragma unroll
        for (int i = 0; i < 4; i++) {
            int u = i * 256 + tid;
            int row = u >> 3, ku = u & 7;
            uint32_t bo = row * 128 + ku * 16;
            uint32_t sw = bo ^ ((bo >> 3) & 0x70);
            cp16(sbuf + 16384 + sw, Wb + (size_t)row * 1536 + c * 128 + ku * 16);
        }
        cp_commit();
    };

    float acc[2][8][4];
#pragma unroll
    for (int i = 0; i < 2; i++)
#pragma unroll
        for (int j = 0; j < 8; j++)
#pragma unroll
            for (int e = 0; e < 4; e++) acc[i][j][e] = 0.f;

    const uint32_t xorm = (uint32_t)(lane & 7) << 4;
    const int arow = wm * 32 + (lane & 15);
    const int ahi  = lane >> 4;
    const int brow = wn * 64 + ((lane >> 4) & 1) * 8 + (lane & 7);
    const int bhi  = (lane >> 3) & 1;

    load_stage(0, 0);
    load_stage(1, 1);

    for (int c = 0; c < 12; ++c) {
        if (c < 11) { asm volatile("cp.async.wait_group 1;" ::: "memory"); }
        else        { asm volatile("cp.async.wait_group 0;" ::: "memory"); }
        __syncthreads();

        const uint32_t sbuf  = sb + (c & 1) * STAGE_BYTES;
        const uint32_t sbufB = sbuf + 16384;

#pragma unroll
        for (int ks = 0; ks < 4; ks++) {
            uint32_t a[2][4];
#pragma unroll
            for (int mm = 0; mm < 2; mm++) {
                uint32_t bo = (uint32_t)(arow + mm * 16) * 128
                            + ((uint32_t)((ks * 2 + ahi) * 16) ^ xorm);
                ldsm_x4(a[mm], sbuf + bo);
            }
            uint32_t b[4][4];
#pragma unroll
            for (int jp = 0; jp < 4; jp++) {
                uint32_t bo = (uint32_t)(brow + jp * 16) * 128
                            + ((uint32_t)((ks * 2 + bhi) * 16) ^ xorm);
                ldsm_x4(b[jp], sbufB + bo);
            }
#pragma unroll
            for (int mm = 0; mm < 2; mm++)
#pragma unroll
                for (int jn = 0; jn < 8; jn++)
                    mma16816(acc[mm][jn], a[mm], &b[jn >> 1][(jn & 1) * 2]);
        }
        __syncthreads();
        if (c + 2 < 12) load_stage(c + 2, c & 1);
    }

    const int r0 = bm + wm * 32 + (lane >> 2);
    const int c0 = bn + wn * 64 + (lane & 3) * 2;
#pragma unroll
    for (int mm = 0; mm < 2; mm++) {
#pragma unroll
        for (int jn = 0; jn < 8; jn++) {
            const int row = r0 + mm * 16;
            const int col = c0 + jn * 8;
            float v0 = acc[mm][jn][0], v1 = acc[mm][jn][1];
            float v2 = acc[mm][jn][2], v3 = acc[mm][jn][3];
            if (WITH_BIAS) {
                float b0 = bias[col], b1 = bias[col + 1];
                v0 += b0; v1 += b1; v2 += b0; v3 += b1;
            }
            if (ACT == 1) {
                v0 = tanhf(v0); v1 = tanhf(v1); v2 = tanhf(v2); v3 = tanhf(v3);
            }
            *(float2*)(C + (size_t)row * N + col)       = make_float2(v0, v1);
            *(float2*)(C + (size_t)(row + 8) * N + col) = make_float2(v2, v3);
        }
    }
}

// ---------------------------------------------------------------------------
// Sampler v4: identical gather math to v3, but the epilogue writes the
// split-bf16 extended layout [hi | lo | hi] directly into g_samp_ext
// (same rounding the convert kernel performed -> identical numerics),
// killing a 34MB fp32 write + 34MB read + one kernel launch.
// ---------------------------------------------------------------------------
__global__ void __launch_bounds__(256) sampler_kernel(
    const float* __restrict__ v,
    const float* __restrict__ off,
    const float* __restrict__ attn,
    const float* __restrict__ refp,
    __nv_bfloat16* __restrict__ outp)   // [MQ, 768] ext layout
{
    __shared__ int   s_pos[8][16][4];
    __shared__ float s_w  [8][16][4];

    const int wslot = threadIdx.x >> 5;
    const int wid   = blockIdx.x * 8 + wslot;
    const int lane  = threadIdx.x & 31;
    const int h     = wid & 7;
    const size_t bq = (size_t)(wid >> 3);
    const int b     = wid >> 16;

    const int r   = lane & 15;
    const int lev = r >> 2;
    const int Wl  = 128 >> lev;
    const int start = (65536 - ((Wl * Wl) << 2)) / 3;

    float logit = attn[bq * 128 + h * 16 + r];
    float m = logit;
#pragma unroll
    for (int s = 1; s < 16; s <<= 1)
        m = fmaxf(m, __shfl_xor_sync(0xffffffffu, m, s));
    float e = __expf(logit - m);
    float ssum = e;
#pragma unroll
    for (int s = 1; s < 16; s <<= 1)
        ssum += __shfl_xor_sync(0xffffffffu, ssum, s);
    const float wgt = e / ssum;

    const float rx = refp[bq * 8 + lev * 2 + 0];
    const float ry = refp[bq * 8 + lev * 2 + 1];
    const float ox = off[bq * 256 + h * 32 + r * 2 + 0];
    const float oy = off[bq * 256 + h * 32 + r * 2 + 1];
    const float x = fminf(fmaxf(rx + ox, -1.f), 1.f);
    const float y = fminf(fmaxf(ry + oy, -1.f), 1.f);
    const float scale = 0.5f * (float)(Wl - 1);
    const float fx = (x + 1.f) * scale;
    const float fy = (y + 1.f) * scale;
    const float x0f = floorf(fx), y0f = floorf(fy);
    const float wx = fx - x0f,    wy = fy - y0f;
    const int x0 = min(max((int)x0f, 0), Wl - 1);
    const int x1 = min(x0 + 1, Wl - 1);
    const int y0 = min(max((int)y0f, 0), Wl - 1);
    const int y1 = min(y0 + 1, Wl - 1);

    if (lane < 16) {
        s_pos[wslot][r][0] = start + y0 * Wl + x0;
        s_pos[wslot][r][1] = start + y0 * Wl + x1;
        s_pos[wslot][r][2] = start + y1 * Wl + x0;
        s_pos[wslot][r][3] = start + y1 * Wl + x1;
        s_w  [wslot][r][0] = wgt * (1.f - wx) * (1.f - wy);
        s_w  [wslot][r][1] = wgt * wx * (1.f - wy);
        s_w  [wslot][r][2] = wgt * (1.f - wx) * wy;
        s_w  [wslot][r][3] = wgt * wx * wy;
    }
    __syncwarp();

    const int c = lane >> 3;
    const int k = lane & 7;
    const float* vbase = v + (size_t)b * VLENv * Ee + h * HDd + k * 4;

    float ax = 0.f, ay = 0.f, az = 0.f, aw = 0.f;
#pragma unroll
    for (int t = 0; t < 16; t++) {
        const int   pos = s_pos[wslot][t][c];
        const float wc  = s_w  [wslot][t][c];
        const float4 d = *(const float4*)(vbase + (size_t)pos * Ee);
        ax = fmaf(wc, d.x, ax);
        ay = fmaf(wc, d.y, ay);
        az = fmaf(wc, d.z, az);
        aw = fmaf(wc, d.w, aw);
    }
#pragma unroll
    for (int s = 8; s < 32; s <<= 1) {
        ax += __shfl_xor_sync(0xffffffffu, ax, s);
        ay += __shfl_xor_sync(0xffffffffu, ay, s);
        az += __shfl_xor_sync(0xffffffffu, az, s);
        aw += __shfl_xor_sync(0xffffffffu, aw, s);
    }

    if (lane < 8) {
        // split-bf16 ext store: hi @ col, lo @ col+256, hi @ col+512
        __nv_bfloat16 h0 = __float2bfloat16(ax);
        __nv_bfloat16 h1 = __float2bfloat16(ay);
        __nv_bfloat16 h2 = __float2bfloat16(az);
        __nv_bfloat16 h3 = __float2bfloat16(aw);
        union { __nv_bfloat162 v2[2]; uint2 u; } hi, lo;
        hi.v2[0].x = h0; hi.v2[0].y = h1; hi.v2[1].x = h2; hi.v2[1].y = h3;
        lo.v2[0].x = __float2bfloat16(ax - __bfloat162float(h0));
        lo.v2[0].y = __float2bfloat16(ay - __bfloat162float(h1));
        lo.v2[1].x = __float2bfloat16(az - __bfloat162float(h2));
        lo.v2[1].y = __float2bfloat16(aw - __bfloat162float(h3));
        __nv_bfloat16* o = outp + bq * KE + h * HDd + k * 4;
        *(uint2*)(o)       = hi.u;
        *(uint2*)(o + 256) = lo.u;
        *(uint2*)(o + 512) = hi.u;
    }
}

// ---------------------------------------------------------------------------
// kernel_launch — forked-graph schedule:
//   branch A (stream 0): conv_val -> GEMM1(value)
//   branch B (s1):       conv_w4, conv_q -> GEMM2(off) -> GEMM3(attn)
//   join -> sampler (writes samp_ext) -> GEMM4(out)
// inputs: 0 queries, 1 ref_points, 2 value, 3 spatial_shapes,
//         4 V_W, 5 off_W, 6 off_b, 7 attn_W, 8 attn_b, 9 out_W
// ---------------------------------------------------------------------------
extern "C" void kernel_launch(void* const* d_in, const int* in_sizes, int n_in,
                              void* d_out, int out_size)
{
    const float* queries = (const float*)d_in[0];
    const float* refp    = (const float*)d_in[1];
    const float* value   = (const float*)d_in[2];
    const float* V_W     = (const float*)d_in[4];
    const float* off_W   = (const float*)d_in[5];
    const float* off_b   = (const float*)d_in[6];
    const float* attn_W  = (const float*)d_in[7];
    const float* attn_b  = (const float*)d_in[8];
    const float* out_W   = (const float*)d_in[9];
    float* out = (float*)d_out;

    float *pv, *poff, *pattn;
    __nv_bfloat16 *pval_e, *pq_e, *psamp_e, *pw_e;
    cudaGetSymbolAddress((void**)&pv,      g_v);
    cudaGetSymbolAddress((void**)&poff,    g_off);
    cudaGetSymbolAddress((void**)&pattn,   g_attn);
    cudaGetSymbolAddress((void**)&pval_e,  g_val_ext);
    cudaGetSymbolAddress((void**)&pq_e,    g_q_ext);
    cudaGetSymbolAddress((void**)&psamp_e, g_samp_ext);
    cudaGetSymbolAddress((void**)&pw_e,    g_w_ext);
    __nv_bfloat16* w_v    = pw_e + 0 * (size_t)256 * KE;
    __nv_bfloat16* w_off  = pw_e + 1 * (size_t)256 * KE;
    __nv_bfloat16* w_attn = pw_e + 2 * (size_t)256 * KE;
    __nv_bfloat16* w_out  = pw_e + 3 * (size_t)256 * KE;

    cudaFuncSetAttribute(mm_hmma<0, 0>, cudaFuncAttributeMaxDynamicSharedMemorySize, SMEM_TOTAL_MM);
    cudaFuncSetAttribute(mm_hmma<1, 1>, cudaFuncAttributeMaxDynamicSharedMemorySize, SMEM_TOTAL_MM);
    cudaFuncSetAttribute(mm_hmma<0, 1>, cudaFuncAttributeMaxDynamicSharedMemorySize, SMEM_TOTAL_MM);

    // side stream + fork/join events (host objects; created per call — the
    // harness calls kernel_launch only a handful of times, replays the graph)
    cudaStream_t s1;
    cudaStreamCreateWithFlags(&s1, cudaStreamNonBlocking);
    cudaEvent_t eFork, eJoin;
    cudaEventCreateWithFlags(&eFork, cudaEventDisableTiming);
    cudaEventCreateWithFlags(&eJoin, cudaEventDisableTiming);

    cudaEventRecord(eFork, 0);
    cudaStreamWaitEvent(s1, eFork, 0);

    // ---- branch A (stream 0): value path
    convert_ext<0><<<(MV * 128 + 255) / 256, 256>>>(value, pval_e, MV);
    mm_hmma<0, 0><<<dim3(2, MV / 128), 256, SMEM_TOTAL_MM>>>(pval_e, w_v, nullptr, pv, MV, 256);

    // ---- branch B (s1): weights + query path
    convert_w4<<<448, 256, 0, s1>>>(V_W, off_W, attn_W, out_W, w_v, w_off, w_attn, w_out);
    convert_ext<0><<<(MQ * 128 + 255) / 256, 256, 0, s1>>>(queries, pq_e, MQ);
    mm_hmma<1, 1><<<dim3(2, MQ / 128), 256, SMEM_TOTAL_MM, s1>>>(pq_e, w_off, off_b, poff, MQ, 256);
    mm_hmma<0, 1><<<dim3(1, MQ / 128), 256, SMEM_TOTAL_MM, s1>>>(pq_e, w_attn, attn_b, pattn, MQ, 128);

    cudaEventRecord(eJoin, s1);
    cudaStreamWaitEvent(0, eJoin, 0);

    // ---- join: sampler (writes split-bf16 ext directly) -> final projection
    sampler_kernel<<<(Bb * Qq * Hh) / 8, 256>>>(pv, poff, pattn, refp, psamp_e);
    mm_hmma<0, 0><<<dim3(2, MQ / 128), 256, SMEM_TOTAL_MM>>>(psamp_e, w_out, nullptr, out, MQ, 256);
}